// round 2
// baseline (speedup 1.0000x reference)
#include <cuda_runtime.h>
#include <cstdint>

typedef unsigned long long ull;

#define M_OUT   8192
#define N_BATCH 4096
#define K_IN    512
#define K_SEL   204   // max(1, int(0.05 * 4096))

#define BM 128
#define BN 128
#define BK 16

// Scratch: logits stored column-major-by-output: g_logits[o][b]
__device__ float    g_logits[(size_t)M_OUT * N_BATCH];
__device__ unsigned g_tau[M_OUT];
__device__ int      g_cut[M_OUT];   // last included batch index among ties

// ---------------------------------------------------------------------------
// helpers
// ---------------------------------------------------------------------------
__device__ __forceinline__ ull fma2(ull a, ull b, ull c) {
    ull d;
    asm("fma.rn.f32x2 %0, %1, %2, %3;" : "=l"(d) : "l"(a), "l"(b), "l"(c));
    return d;
}

__device__ __forceinline__ ull add2(ull a, ull b) {
    ull d;
    asm("add.rn.f32x2 %0, %1, %2;" : "=l"(d) : "l"(a), "l"(b));
    return d;
}

__device__ __forceinline__ ull pack2(float x) {
    ull d;
    unsigned u = __float_as_uint(x);
    asm("mov.b64 %0, {%1, %1};" : "=l"(d) : "r"(u));
    return d;
}

// monotone float -> uint key (ascending order preserved)
__device__ __forceinline__ unsigned fkey(float f) {
    unsigned u = __float_as_uint(f);
    return u ^ ((u & 0x80000000u) ? 0xFFFFFFFFu : 0x80000000u);
}

// ---------------------------------------------------------------------------
// GEMM: g_logits[o][b] = (sum_{k ascending} W[o][k]*X[b][k]) + bias[o]
// Accumulator starts at 0 and k runs strictly ascending (single FMA chain per
// element) to match the reference's fp32 rounding; bias added once at the end.
// ---------------------------------------------------------------------------
__global__ __launch_bounds__(256, 2) void gemm_kernel(
    const float* __restrict__ W, const float* __restrict__ X,
    const float* __restrict__ bias) {
    __shared__ float As2[BK][2 * BM];  // duplicated pairs: As2[k][2m]=As2[k][2m+1]
    __shared__ float Bs[BK][BN];

    const int tid = threadIdx.x;
    const int tx = tid & 15;   // n direction
    const int ty = tid >> 4;   // m direction
    const int m0 = blockIdx.y * BM;
    const int n0 = blockIdx.x * BN;

    ull acc[2][4][2][2];
#pragma unroll
    for (int ih = 0; ih < 2; ih++)
#pragma unroll
        for (int i = 0; i < 4; i++)
#pragma unroll
            for (int jh = 0; jh < 2; jh++) {
                acc[ih][i][jh][0] = 0ull;
                acc[ih][i][jh][1] = 0ull;
            }

    // global tile loading: 512 float4 per matrix per stage, 2 per thread
    const int lrow = tid >> 2;  // 0..63 (+64 second iter)
    const int lkq  = tid & 3;   // which float4 along k
    const float* wp = W + (size_t)(m0 + lrow) * K_IN + lkq * 4;
    const float* xp = X + (size_t)(n0 + lrow) * K_IN + lkq * 4;

    float4 ra[2], rb[2];
#pragma unroll
    for (int it = 0; it < 2; it++) {
        ra[it] = *(const float4*)(wp + (size_t)it * 64 * K_IN);
        rb[it] = *(const float4*)(xp + (size_t)it * 64 * K_IN);
    }

    for (int kk = 0; kk < K_IN; kk += BK) {
        __syncthreads();
#pragma unroll
        for (int it = 0; it < 2; it++) {
            const int row = lrow + it * 64;
            const float a4[4] = {ra[it].x, ra[it].y, ra[it].z, ra[it].w};
            const float b4[4] = {rb[it].x, rb[it].y, rb[it].z, rb[it].w};
#pragma unroll
            for (int j = 0; j < 4; j++) {
                As2[lkq * 4 + j][2 * row]     = a4[j];
                As2[lkq * 4 + j][2 * row + 1] = a4[j];
                Bs[lkq * 4 + j][row]          = b4[j];
            }
        }
        __syncthreads();
        if (kk + BK < K_IN) {
#pragma unroll
            for (int it = 0; it < 2; it++) {
                ra[it] = *(const float4*)(wp + (size_t)it * 64 * K_IN + kk + BK);
                rb[it] = *(const float4*)(xp + (size_t)it * 64 * K_IN + kk + BK);
            }
        }
#pragma unroll
        for (int k = 0; k < BK; k++) {
            const ulonglong2 a00 = *(const ulonglong2*)&As2[k][8 * ty];
            const ulonglong2 a01 = *(const ulonglong2*)&As2[k][8 * ty + 4];
            const ulonglong2 a10 = *(const ulonglong2*)&As2[k][128 + 8 * ty];
            const ulonglong2 a11 = *(const ulonglong2*)&As2[k][128 + 8 * ty + 4];
            const ulonglong2 bv0 = *(const ulonglong2*)&Bs[k][4 * tx];
            const ulonglong2 bv1 = *(const ulonglong2*)&Bs[k][64 + 4 * tx];
            const ull A[2][4]  = {{a00.x, a00.y, a01.x, a01.y},
                                  {a10.x, a10.y, a11.x, a11.y}};
            const ull Bv[2][2] = {{bv0.x, bv0.y}, {bv1.x, bv1.y}};
#pragma unroll
            for (int ih = 0; ih < 2; ih++)
#pragma unroll
                for (int i = 0; i < 4; i++)
#pragma unroll
                    for (int jh = 0; jh < 2; jh++)
#pragma unroll
                        for (int jj = 0; jj < 2; jj++)
                            acc[ih][i][jh][jj] =
                                fma2(A[ih][i], Bv[jh][jj], acc[ih][i][jh][jj]);
        }
    }

    // epilogue: add bias (single rounded f32 add, matching reference), store
#pragma unroll
    for (int ih = 0; ih < 2; ih++)
#pragma unroll
        for (int i = 0; i < 4; i++) {
            const int row = m0 + ih * 64 + ty * 4 + i;
            const ull bv = pack2(bias[row]);
            float* crow = g_logits + (size_t)row * N_BATCH + n0;
#pragma unroll
            for (int jh = 0; jh < 2; jh++) {
                const int col = jh * 64 + tx * 4;
                *(ull*)(crow + col)     = add2(acc[ih][i][jh][0], bv);
                *(ull*)(crow + col + 2) = add2(acc[ih][i][jh][1], bv);
            }
        }
}

// ---------------------------------------------------------------------------
// Per-column rank-K_SEL selection via MSB-first 8-bit radix select, PLUS exact
// tie handling: g_tau[o] = key of the K_SEL-th largest, g_cut[o] = batch index
// of the last tau-valued element included (ties broken by lower index, as in
// lax.top_k).
// ---------------------------------------------------------------------------
__global__ __launch_bounds__(256) void select_kernel() {
    __shared__ unsigned skeys[N_BATCH];
    __shared__ unsigned hist[256];
    __shared__ unsigned s_prefix;
    __shared__ int s_rem;

    const int tid = threadIdx.x;
    const int o = blockIdx.x;
    const float* col = g_logits + (size_t)o * N_BATCH;

    for (int i = tid; i < N_BATCH; i += 256) skeys[i] = fkey(col[i]);
    if (tid == 0) { s_prefix = 0u; s_rem = K_SEL; }

    const unsigned himasks[4] = {0u, 0xFF000000u, 0xFFFF0000u, 0xFFFFFF00u};
#pragma unroll
    for (int pass = 0; pass < 4; pass++) {
        const int shift = 24 - 8 * pass;
        __syncthreads();
        hist[tid] = 0;
        __syncthreads();
        const unsigned hm = himasks[pass];
        const unsigned pfx = s_prefix;
        for (int i = tid; i < N_BATCH; i += 256) {
            const unsigned u = skeys[i];
            if ((u & hm) == (pfx & hm)) atomicAdd(&hist[(u >> shift) & 255], 1u);
        }
        __syncthreads();
        if (tid == 0) {
            unsigned cum = 0;
            int d;
            for (d = 255; d >= 0; d--) {
                cum += hist[d];
                if ((int)cum >= s_rem) break;
            }
            s_rem -= (int)(cum - hist[d]);
            s_prefix = pfx | ((unsigned)d << shift);
        }
    }
    __syncthreads();

    // tie resolution: find index of the s_rem-th occurrence of tau (ascending)
    const unsigned tau = s_prefix;
    const int rem = s_rem;
    const int base = tid * 16;
    int cnt = 0;
#pragma unroll
    for (int j = 0; j < 16; j++) cnt += (skeys[base + j] == tau) ? 1 : 0;
    __syncthreads();
    hist[tid] = (unsigned)cnt;
    __syncthreads();
    // inclusive Hillis-Steele scan over 256 entries
    for (int off = 1; off < 256; off <<= 1) {
        const unsigned v = hist[tid];
        const unsigned a = (tid >= off) ? hist[tid - off] : 0u;
        __syncthreads();
        hist[tid] = v + a;
        __syncthreads();
    }
    const int incl = (int)hist[tid];
    const int excl = incl - cnt;
    if (excl < rem && rem <= incl) {
        int need = rem - excl;
        for (int j = 0; j < 16; j++) {
            if (skeys[base + j] == tau && --need == 0) {
                g_cut[o] = base + j;
                break;
            }
        }
    }
    if (tid == 0) g_tau[o] = tau;
}

// ---------------------------------------------------------------------------
// Mask writer with 32x32 SMEM transpose: reads g_logits[o][b] coalesced,
// writes out[b][o] coalesced. mask = key > tau, or key == tau with b <= cut.
// ---------------------------------------------------------------------------
__global__ __launch_bounds__(256) void mask_kernel(float* __restrict__ out) {
    __shared__ unsigned tile[32][33];
    __shared__ unsigned stau[32];
    __shared__ int scut[32];
    const int tx = threadIdx.x;  // 0..31
    const int ty = threadIdx.y;  // 0..7
    const int b0 = blockIdx.x * 32;
    const int o0 = blockIdx.y * 32;

    if (ty == 0) {
        stau[tx] = g_tau[o0 + tx];
        scut[tx] = g_cut[o0 + tx];
    }
#pragma unroll
    for (int r = ty; r < 32; r += 8)
        tile[r][tx] = fkey(g_logits[(size_t)(o0 + r) * N_BATCH + b0 + tx]);
    __syncthreads();

    const unsigned tau = stau[tx];
    const int cut = scut[tx];
#pragma unroll
    for (int r = ty; r < 32; r += 8) {
        const unsigned k = tile[tx][r];
        const int b = b0 + r;
        out[(size_t)b * M_OUT + o0 + tx] =
            (k > tau || (k == tau && b <= cut)) ? 1.0f : 0.0f;
    }
}

// ---------------------------------------------------------------------------
extern "C" void kernel_launch(void* const* d_in, const int* in_sizes, int n_in,
                              void* d_out, int out_size) {
    const float* x = (const float*)d_in[0];  // [4096, 512]
    const float* W = (const float*)d_in[1];  // [8192, 512]
    const float* b = (const float*)d_in[2];  // [8192]
    float* out = (float*)d_out;              // [4096, 8192]

    dim3 ggrid(N_BATCH / BN, M_OUT / BM);  // (32, 64)
    gemm_kernel<<<ggrid, 256>>>(W, x, b);
    select_kernel<<<M_OUT, 256>>>();
    mask_kernel<<<dim3(N_BATCH / 32, M_OUT / 32), dim3(32, 8)>>>(out);
}

// round 4
// speedup vs baseline: 1.5439x; 1.5439x over previous
#include <cuda_runtime.h>
#include <cuda_fp16.h>
#include <cstdint>

typedef unsigned long long ull;

#define M_OUT   8192
#define N_BATCH 4096
#define K_IN    512
#define K_SEL   204
#define CAP     64
#define EPS     3e-3f
#define ZC      1.64485f   // Phi^-1(0.95)
#define ZSTEP   0.035f

// GEMM tiling
#define TM 128
#define TN 128
#define SA 24            // padded halves per smem row (16 data + 8 pad)
#define NKS (K_IN / 16)  // 32 k-steps

// ---------------------------------------------------------------------------
// scratch
// ---------------------------------------------------------------------------
__device__ float  g_logits[(size_t)M_OUT * N_BATCH];
__device__ __half g_Wh[(size_t)M_OUT * K_IN];
__device__ __half g_Xh[(size_t)N_BATCH * K_IN];
__device__ unsigned g_kh[M_OUT];
__device__ int      g_r[M_OUT];
__device__ int      g_ucnt[M_OUT];
__device__ int      g_uidx[(size_t)M_OUT * CAP];

// ---------------------------------------------------------------------------
// helpers
// ---------------------------------------------------------------------------
__device__ __forceinline__ uint32_t smem_u32(const void* p) {
    uint32_t a;
    asm("{ .reg .u64 t; cvta.to.shared.u64 t, %1; cvt.u32.u64 %0, t; }"
        : "=r"(a) : "l"(p));
    return a;
}
__device__ __forceinline__ void cpasync16(uint32_t dst, const void* src) {
    asm volatile("cp.async.cg.shared.global [%0], [%1], 16;"
                 :: "r"(dst), "l"(src) : "memory");
}
#define CP_COMMIT() asm volatile("cp.async.commit_group;" ::: "memory")
#define CP_WAIT(n)  asm volatile("cp.async.wait_group %0;" :: "n"(n) : "memory")

__device__ __forceinline__ void mma16816(float* c, const uint32_t* a,
                                         const uint32_t* b) {
    asm volatile(
        "mma.sync.aligned.m16n8k16.row.col.f32.f16.f16.f32 "
        "{%0,%1,%2,%3}, {%4,%5,%6,%7}, {%8,%9}, {%0,%1,%2,%3};"
        : "+f"(c[0]), "+f"(c[1]), "+f"(c[2]), "+f"(c[3])
        : "r"(a[0]), "r"(a[1]), "r"(a[2]), "r"(a[3]), "r"(b[0]), "r"(b[1]));
}

// monotone float -> uint key
__device__ __forceinline__ unsigned fkey(float f) {
    unsigned u = __float_as_uint(f);
    return u ^ ((u & 0x80000000u) ? 0xFFFFFFFFu : 0x80000000u);
}

// ---------------------------------------------------------------------------
// 1) convert fp32 -> fp16
// ---------------------------------------------------------------------------
#define WQ ((size_t)M_OUT * K_IN / 4)
#define XQ ((size_t)N_BATCH * K_IN / 4)
__global__ __launch_bounds__(256) void split_kernel(const float* __restrict__ W,
                                                    const float* __restrict__ X) {
    size_t q = (size_t)blockIdx.x * 256 + threadIdx.x;
    const float4* src;
    __half2* dst;
    if (q < WQ) {
        src = (const float4*)W;
        dst = (__half2*)g_Wh;
    } else {
        q -= WQ;
        if (q >= XQ) return;
        src = (const float4*)X;
        dst = (__half2*)g_Xh;
    }
    float4 v = src[q];
    dst[q * 2]     = __half2(__float2half_rn(v.x), __float2half_rn(v.y));
    dst[q * 2 + 1] = __half2(__float2half_rn(v.z), __float2half_rn(v.w));
}

// ---------------------------------------------------------------------------
// 2) fp16 HMMA GEMM: g_logits[o][b] = W_h[o,:] . X_h[b,:] + bias[o]
//    CTA 128x128, 8 warps (2x4), warp tile 64x32, BK=16, 3-stage cp.async
// ---------------------------------------------------------------------------
__global__ __launch_bounds__(256, 2) void gemm_kernel(const float* __restrict__ bias) {
    __shared__ __half As[3][TM * SA];
    __shared__ __half Bs[3][TN * SA];

    const int tid = threadIdx.x;
    const int w = tid >> 5, lane = tid & 31;
    const int wm = w >> 2, wn = w & 3;
    const int g = lane >> 2, tg = lane & 3;
    const int m0 = blockIdx.y * TM, n0 = blockIdx.x * TN;

    // per-thread copy slots: 2 x 16B
    const int c0row = tid >> 1, c0half = tid & 1;  // A rows 0..127
    const uint32_t asA = smem_u32(&As[0][0]);
    const uint32_t asB = smem_u32(&Bs[0][0]);
    const __half* srcA = g_Wh + (size_t)(m0 + c0row) * K_IN + c0half * 8;
    const __half* srcB = g_Xh + (size_t)(n0 + c0row) * K_IN + c0half * 8;
    const uint32_t dstA = asA + c0row * (SA * 2) + c0half * 16;
    const uint32_t dstB = asB + c0row * (SA * 2) + c0half * 16;

#define ISSUE(s) do {                                          \
        const int _b = (s) % 3;                                \
        cpasync16(dstA + _b * (TM * SA * 2), srcA + (s) * 16); \
        cpasync16(dstB + _b * (TN * SA * 2), srcB + (s) * 16); \
        CP_COMMIT();                                           \
    } while (0)

    ISSUE(0);
    ISSUE(1);

    float acc[4][4][4];
#pragma unroll
    for (int i = 0; i < 4; i++)
#pragma unroll
        for (int j = 0; j < 4; j++)
#pragma unroll
            for (int r = 0; r < 4; r++) acc[i][j][r] = 0.f;

    for (int s = 0; s < NKS; s++) {
        if (s < NKS - 1) CP_WAIT(1); else CP_WAIT(0);
        __syncthreads();
        if (s + 2 < NKS) ISSUE(s + 2);

        const __half* Ab = As[s % 3];
        const __half* Bb = Bs[s % 3];
        uint32_t a[4][4], b[4][2];
#pragma unroll
        for (int i = 0; i < 4; i++) {
            const int r0 = wm * 64 + i * 16 + g;
            a[i][0] = *(const uint32_t*)&Ab[r0 * SA + tg * 2];
            a[i][1] = *(const uint32_t*)&Ab[(r0 + 8) * SA + tg * 2];
            a[i][2] = *(const uint32_t*)&Ab[r0 * SA + tg * 2 + 8];
            a[i][3] = *(const uint32_t*)&Ab[(r0 + 8) * SA + tg * 2 + 8];
        }
#pragma unroll
        for (int j = 0; j < 4; j++) {
            const int n = wn * 32 + j * 8 + g;
            b[j][0] = *(const uint32_t*)&Bb[n * SA + tg * 2];
            b[j][1] = *(const uint32_t*)&Bb[n * SA + tg * 2 + 8];
        }
#pragma unroll
        for (int i = 0; i < 4; i++)
#pragma unroll
            for (int j = 0; j < 4; j++) mma16816(acc[i][j], a[i], b[j]);
        __syncthreads();
    }

    // epilogue
#pragma unroll
    for (int i = 0; i < 4; i++) {
        const int o_lo = m0 + wm * 64 + i * 16 + g;
        const float b_lo = bias[o_lo];
        const float b_hi = bias[o_lo + 8];
#pragma unroll
        for (int j = 0; j < 4; j++) {
            const int n = n0 + wn * 32 + j * 8 + tg * 2;
            float2 v0 = {acc[i][j][0] + b_lo, acc[i][j][1] + b_lo};
            float2 v1 = {acc[i][j][2] + b_hi, acc[i][j][3] + b_hi};
            *(float2*)(g_logits + (size_t)o_lo * N_BATCH + n) = v0;
            *(float2*)(g_logits + (size_t)(o_lo + 8) * N_BATCH + n) = v1;
        }
    }
#undef ISSUE
}

// ---------------------------------------------------------------------------
// 3) select: analytic threshold grid + band classification (no histograms)
// ---------------------------------------------------------------------------
__global__ __launch_bounds__(256) void select_kernel(const float* __restrict__ W,
                                                     const float* __restrict__ bias) {
    __shared__ float s_w2[8];
    __shared__ int totals[16];
    __shared__ int sA, scnt;

    const int tid = threadIdx.x;
    const int o = blockIdx.x;

    // sigma^2 = sum_k W[o][k]^2
    float w2 = 0.f;
    for (int k = tid; k < K_IN; k += 256) {
        const float wv = W[(size_t)o * K_IN + k];
        w2 = __fmaf_rn(wv, wv, w2);
    }
#pragma unroll
    for (int off = 16; off; off >>= 1) w2 += __shfl_xor_sync(0xffffffffu, w2, off);
    if ((tid & 31) == 0) s_w2[tid >> 5] = w2;
    if (tid < 16) totals[tid] = 0;
    if (tid == 0) { sA = 0; scnt = 0; }
    __syncthreads();
    float sig2 = 0.f;
#pragma unroll
    for (int i = 0; i < 8; i++) sig2 += s_w2[i];
    const float sigma = sqrtf(sig2);
    const float tc = bias[o] + ZC * sigma;
    const float step = ZSTEP * sigma;

    // load column into registers
    const float* col = g_logits + (size_t)o * N_BATCH;
    float v[16];
#pragma unroll
    for (int q = 0; q < 16; q++) v[q] = col[tid + 256 * q];

    // count 16 thresholds
    float t[16];
    int cnt[16];
#pragma unroll
    for (int i = 0; i < 16; i++) {
        t[i] = tc + (float)(i - 8) * step;
        cnt[i] = 0;
    }
#pragma unroll
    for (int q = 0; q < 16; q++) {
        const float x = v[q];
#pragma unroll
        for (int i = 0; i < 16; i++) cnt[i] += (x > t[i]) ? 1 : 0;
    }
#pragma unroll
    for (int i = 0; i < 16; i++) {
        const int s = __reduce_add_sync(0xffffffffu, cnt[i]);
        if ((tid & 31) == 0 && s) atomicAdd(&totals[i], s);
    }
    __syncthreads();

    int js = -1;
#pragma unroll
    for (int i = 0; i < 16; i++)
        if (totals[i] >= K_SEL) js = i;
    if (js < 0 || js == 15) {  // grid miss -> exact fallback
        if (tid == 0) g_ucnt[o] = CAP + 1;
        return;
    }
    const float T_hi = t[js + 1] + EPS;
    const float T_lo = t[js] - EPS;

    int a = 0;
#pragma unroll
    for (int q = 0; q < 16; q++) {
        const float x = v[q];
        if (x > T_hi) a++;
        else if (x > T_lo) {
            const int p = atomicAdd(&scnt, 1);
            if (p < CAP) g_uidx[(size_t)o * CAP + p] = tid + 256 * q;
        }
    }
    a = __reduce_add_sync(0xffffffffu, a);
    if ((tid & 31) == 0 && a) atomicAdd(&sA, a);
    __syncthreads();
    if (tid == 0) {
        if (scnt > CAP) {
            g_ucnt[o] = CAP + 1;  // fallback
        } else {
            g_ucnt[o] = scnt;
            g_r[o] = K_SEL - sA;
            g_kh[o] = fkey(T_hi);
        }
    }
}

// ---------------------------------------------------------------------------
// 4) mask: out[b][o] = (key(logit) > kh[o])
// ---------------------------------------------------------------------------
__global__ __launch_bounds__(256) void mask_kernel(float* __restrict__ out) {
    __shared__ unsigned tile[32][33];
    __shared__ unsigned stau[32];
    const int tx = threadIdx.x, ty = threadIdx.y;
    const int b0 = blockIdx.x * 32, o0 = blockIdx.y * 32;

    if (ty == 0) stau[tx] = g_kh[o0 + tx];
#pragma unroll
    for (int r = ty; r < 32; r += 8)
        tile[r][tx] = fkey(g_logits[(size_t)(o0 + r) * N_BATCH + b0 + tx]);
    __syncthreads();
    const unsigned kh = stau[tx];
#pragma unroll
    for (int r = ty; r < 32; r += 8)
        out[(size_t)(b0 + r) * M_OUT + o0 + tx] = (tile[tx][r] > kh) ? 1.0f : 0.0f;
}

// ---------------------------------------------------------------------------
// 5) repair: exact fp32 chain on uncertain elements (or whole column fallback)
// ---------------------------------------------------------------------------
__global__ __launch_bounds__(256) void repair_kernel(const float* __restrict__ W,
                                                     const float* __restrict__ X,
                                                     const float* __restrict__ bias,
                                                     float* __restrict__ out) {
    const int o = blockIdx.x;
    const int tid = threadIdx.x;
    const int c = g_ucnt[o];
    if (c == 0) return;

    const float* wr = W + (size_t)o * K_IN;

    if (c <= CAP) {
        __shared__ float vals[CAP];
        __shared__ int idxs[CAP];
        if (tid < c) {
            const int b = g_uidx[(size_t)o * CAP + tid];
            const float* xr = X + (size_t)b * K_IN;
            float acc = 0.f;
            for (int k = 0; k < K_IN; k++) acc = __fmaf_rn(wr[k], xr[k], acc);
            vals[tid] = acc + bias[o];
            idxs[tid] = b;
        }
        __syncthreads();
        if (tid == 0) {
            const int r = g_r[o];
            ull taken = 0;
            for (int rep = 0; rep < r; rep++) {
                int best = -1;
                for (int j = 0; j < c; j++) {
                    if ((taken >> j) & 1ull) continue;
                    if (best < 0 || vals[j] > vals[best] ||
                        (vals[j] == vals[best] && idxs[j] < idxs[best]))
                        best = j;
                }
                taken |= 1ull << best;
                out[(size_t)idxs[best] * M_OUT + o] = 1.0f;
            }
        }
        return;
    }

    // fallback: recompute whole column exactly + exact radix select with ties
    __shared__ unsigned keys[N_BATCH];
    __shared__ unsigned hist[256];
    __shared__ unsigned s_prefix;
    __shared__ int s_rem, s_cut;
    for (int b = tid; b < N_BATCH; b += 256) {
        const float* xr = X + (size_t)b * K_IN;
        float acc = 0.f;
        for (int k = 0; k < K_IN; k++) acc = __fmaf_rn(wr[k], xr[k], acc);
        keys[b] = fkey(acc + bias[o]);
    }
    if (tid == 0) { s_prefix = 0u; s_rem = K_SEL; }
    const unsigned himasks[4] = {0u, 0xFF000000u, 0xFFFF0000u, 0xFFFFFF00u};
#pragma unroll
    for (int pass = 0; pass < 4; pass++) {
        const int shift = 24 - 8 * pass;
        __syncthreads();
        hist[tid] = 0;
        __syncthreads();
        const unsigned hm = himasks[pass];
        const unsigned pfx = s_prefix;
        for (int i = tid; i < N_BATCH; i += 256) {
            const unsigned u = keys[i];
            if ((u & hm) == (pfx & hm)) atomicAdd(&hist[(u >> shift) & 255], 1u);
        }
        __syncthreads();
        if (tid == 0) {
            unsigned cum = 0;
            int d;
            for (d = 255; d >= 0; d--) {
                cum += hist[d];
                if ((int)cum >= s_rem) break;
            }
            s_rem -= (int)(cum - hist[d]);
            s_prefix = pfx | ((unsigned)d << shift);
        }
    }
    __syncthreads();
    const unsigned tau = s_prefix;
    const int rem = s_rem;
    const int base = tid * 16;
    int cnt = 0;
#pragma unroll
    for (int j = 0; j < 16; j++) cnt += (keys[base + j] == tau) ? 1 : 0;
    __syncthreads();
    hist[tid] = (unsigned)cnt;
    __syncthreads();
    for (int off = 1; off < 256; off <<= 1) {
        const unsigned v = hist[tid];
        const unsigned a = (tid >= off) ? hist[tid - off] : 0u;
        __syncthreads();
        hist[tid] = v + a;
        __syncthreads();
    }
    const int incl = (int)hist[tid];
    const int excl = incl - cnt;
    if (excl < rem && rem <= incl) {
        int need = rem - excl;
        for (int j = 0; j < 16; j++) {
            if (keys[base + j] == tau && --need == 0) { s_cut = base + j; break; }
        }
    }
    __syncthreads();
    const int cut = s_cut;
    for (int b = tid; b < N_BATCH; b += 256) {
        const unsigned k = keys[b];
        out[(size_t)b * M_OUT + o] = (k > tau || (k == tau && b <= cut)) ? 1.0f : 0.0f;
    }
}

// ---------------------------------------------------------------------------
extern "C" void kernel_launch(void* const* d_in, const int* in_sizes, int n_in,
                              void* d_out, int out_size) {
    const float* x = (const float*)d_in[0];  // [4096, 512]
    const float* W = (const float*)d_in[1];  // [8192, 512]
    const float* b = (const float*)d_in[2];  // [8192]
    float* out = (float*)d_out;              // [4096, 8192]

    split_kernel<<<(unsigned)((WQ + XQ + 255) / 256), 256>>>(W, x);
    gemm_kernel<<<dim3(N_BATCH / TN, M_OUT / TM), 256>>>(b);
    select_kernel<<<M_OUT, 256>>>(W, b);
    mask_kernel<<<dim3(N_BATCH / 32, M_OUT / 32), dim3(32, 8)>>>(out);
    repair_kernel<<<M_OUT, 256>>>(W, x, b, out);
}

// round 5
// speedup vs baseline: 1.6931x; 1.0967x over previous
#include <cuda_runtime.h>
#include <cuda_fp16.h>
#include <cstdint>

typedef unsigned long long ull;

#define M_OUT   8192
#define N_BATCH 4096
#define K_IN    512
#define K_SEL   204
#define CAP     64
#define DELTA   0.012f     // 2*delta margin (in sigma units) for certain classification
#define ZC      1.64485f   // Phi^-1(0.95)
#define ZSTEP   0.035f

// GEMM tiling
#define TM 128
#define TN 128
#define BKK 32
#define NSTG (K_IN / BKK)   // 16
#define RU 5                // 16B units per smem row (4 data + 1 pad)
#define STG_HALF (128 * RU * 8)  // 5120 halves per stage per matrix
#define STG_BYTES (STG_HALF * 2)

// ---------------------------------------------------------------------------
// scratch
// ---------------------------------------------------------------------------
__device__ __half g_Lh[(size_t)M_OUT * N_BATCH];   // logits (fp16, bias included)
__device__ __half g_Wh[(size_t)M_OUT * K_IN];
__device__ __half g_Xh[(size_t)N_BATCH * K_IN];
__device__ float  g_Thi[M_OUT];
__device__ int    g_r[M_OUT];
__device__ int    g_ucnt[M_OUT];
__device__ int    g_uidx[(size_t)M_OUT * CAP];

// ---------------------------------------------------------------------------
// helpers
// ---------------------------------------------------------------------------
__device__ __forceinline__ uint32_t smem_u32(const void* p) {
    uint32_t a;
    asm("{ .reg .u64 t; cvta.to.shared.u64 t, %1; cvt.u32.u64 %0, t; }"
        : "=r"(a) : "l"(p));
    return a;
}
__device__ __forceinline__ void cpasync16(uint32_t dst, const void* src) {
    asm volatile("cp.async.cg.shared.global [%0], [%1], 16;"
                 :: "r"(dst), "l"(src) : "memory");
}
#define CP_COMMIT() asm volatile("cp.async.commit_group;" ::: "memory")
#define CP_WAIT(n)  asm volatile("cp.async.wait_group %0;" :: "n"(n) : "memory")

__device__ __forceinline__ void ldsm4(uint32_t addr, uint32_t* r) {
    asm volatile("ldmatrix.sync.aligned.m8n8.x4.shared.b16 {%0,%1,%2,%3}, [%4];"
                 : "=r"(r[0]), "=r"(r[1]), "=r"(r[2]), "=r"(r[3]) : "r"(addr));
}
__device__ __forceinline__ void mma16816(float* c, const uint32_t* a,
                                         const uint32_t* b) {
    asm volatile(
        "mma.sync.aligned.m16n8k16.row.col.f32.f16.f16.f32 "
        "{%0,%1,%2,%3}, {%4,%5,%6,%7}, {%8,%9}, {%0,%1,%2,%3};"
        : "+f"(c[0]), "+f"(c[1]), "+f"(c[2]), "+f"(c[3])
        : "r"(a[0]), "r"(a[1]), "r"(a[2]), "r"(a[3]), "r"(b[0]), "r"(b[1]));
}

// ---------------------------------------------------------------------------
// 1) convert fp32 -> fp16
// ---------------------------------------------------------------------------
#define WQ ((size_t)M_OUT * K_IN / 4)
#define XQ ((size_t)N_BATCH * K_IN / 4)
__global__ __launch_bounds__(256) void split_kernel(const float* __restrict__ W,
                                                    const float* __restrict__ X) {
    size_t q = (size_t)blockIdx.x * 256 + threadIdx.x;
    const float4* src;
    __half2* dst;
    if (q < WQ) {
        src = (const float4*)W;
        dst = (__half2*)g_Wh;
    } else {
        q -= WQ;
        if (q >= XQ) return;
        src = (const float4*)X;
        dst = (__half2*)g_Xh;
    }
    float4 v = src[q];
    dst[q * 2]     = __floats2half2_rn(v.x, v.y);
    dst[q * 2 + 1] = __floats2half2_rn(v.z, v.w);
}

// ---------------------------------------------------------------------------
// 2) HMMA GEMM, BK=32, double-buffered cp.async, ldmatrix.x4 operand loads
//    g_Lh[o][b] = fp16( W_h[o,:].X_h[b,:] + bias[o] )
// ---------------------------------------------------------------------------
__global__ __launch_bounds__(256, 2) void gemm_kernel(const float* __restrict__ bias) {
    __shared__ __align__(16) __half As[2][STG_HALF];
    __shared__ __align__(16) __half Bs[2][STG_HALF];

    const int tid = threadIdx.x;
    const int w = tid >> 5, lane = tid & 31;
    const int wm = w >> 2, wn = w & 3;            // warp tile: 64(m) x 32(n)
    const int g = lane >> 2, tg = lane & 3;
    const int m0 = blockIdx.y * TM, n0 = blockIdx.x * TN;

    const uint32_t aB0 = smem_u32(&As[0][0]);
    const uint32_t bB0 = smem_u32(&Bs[0][0]);

    // per-thread copy: 2 chunks of 16B per matrix per stage
    const int id0 = tid, id1 = tid + 256;
    const int r0c = id0 >> 2, c0c = id0 & 3;
    const int r1c = id1 >> 2, c1c = id1 & 3;
    const __half* srcA0 = g_Wh + (size_t)(m0 + r0c) * K_IN + c0c * 8;
    const __half* srcA1 = g_Wh + (size_t)(m0 + r1c) * K_IN + c1c * 8;
    const __half* srcB0 = g_Xh + (size_t)(n0 + r0c) * K_IN + c0c * 8;
    const __half* srcB1 = g_Xh + (size_t)(n0 + r1c) * K_IN + c1c * 8;
    const uint32_t dA0 = (uint32_t)(r0c * RU + c0c) << 4;
    const uint32_t dA1 = (uint32_t)(r1c * RU + c1c) << 4;

#define ISSUE(s) do {                                                  \
        const uint32_t _o = ((s) & 1) * STG_BYTES;                     \
        const int _k = (s) * BKK;                                      \
        cpasync16(aB0 + _o + dA0, srcA0 + _k);                         \
        cpasync16(aB0 + _o + dA1, srcA1 + _k);                         \
        cpasync16(bB0 + _o + dA0, srcB0 + _k);                         \
        cpasync16(bB0 + _o + dA1, srcB1 + _k);                         \
        CP_COMMIT();                                                   \
    } while (0)

    ISSUE(0);
    ISSUE(1);

    float acc[4][4][4];
#pragma unroll
    for (int i = 0; i < 4; i++)
#pragma unroll
        for (int j = 0; j < 4; j++)
#pragma unroll
            for (int r = 0; r < 4; r++) acc[i][j][r] = 0.f;

    // precomputed ldsm lane offsets (in bytes) within a stage
    const uint32_t aLane =
        (uint32_t)((wm * 64 + (lane & 15)) * RU + (lane >> 4)) << 4;
    const uint32_t bLane =
        (uint32_t)((wn * 32 + ((lane >> 4) * 8) + (lane & 7)) * RU +
                   ((lane >> 3) & 1)) << 4;

    for (int s = 0; s < NSTG; s++) {
        if (s == NSTG - 1) CP_WAIT(0); else CP_WAIT(1);
        __syncthreads();
        const uint32_t off = (s & 1) * STG_BYTES;
        const uint32_t aS = aB0 + off, bS = bB0 + off;
#pragma unroll
        for (int j = 0; j < 2; j++) {   // two k16 steps per stage
            uint32_t a[4][4], b[4][2];
#pragma unroll
            for (int i = 0; i < 4; i++)
                ldsm4(aS + aLane + ((uint32_t)(i * 16 * RU) << 4) + (j * 32),
                      a[i]);
#pragma unroll
            for (int jj = 0; jj < 2; jj++) {
                uint32_t r[4];
                ldsm4(bS + bLane + ((uint32_t)(jj * 16 * RU) << 4) + (j * 32), r);
                b[2 * jj][0] = r[0]; b[2 * jj][1] = r[1];
                b[2 * jj + 1][0] = r[2]; b[2 * jj + 1][1] = r[3];
            }
#pragma unroll
            for (int i = 0; i < 4; i++)
#pragma unroll
                for (int jn = 0; jn < 4; jn++) mma16816(acc[i][jn], a[i], b[jn]);
        }
        __syncthreads();
        if (s + 2 < NSTG) ISSUE(s + 2);
    }
#undef ISSUE

    // epilogue: add bias, convert to fp16, store
#pragma unroll
    for (int i = 0; i < 4; i++) {
        const int o_lo = m0 + wm * 64 + i * 16 + g;
        const float b_lo = bias[o_lo];
        const float b_hi = bias[o_lo + 8];
#pragma unroll
        for (int jn = 0; jn < 4; jn++) {
            const int n = n0 + wn * 32 + jn * 8 + tg * 2;
            *(__half2*)(g_Lh + (size_t)o_lo * N_BATCH + n) =
                __floats2half2_rn(acc[i][jn][0] + b_lo, acc[i][jn][1] + b_lo);
            *(__half2*)(g_Lh + (size_t)(o_lo + 8) * N_BATCH + n) =
                __floats2half2_rn(acc[i][jn][2] + b_hi, acc[i][jn][3] + b_hi);
        }
    }
}

// ---------------------------------------------------------------------------
// 3) select: analytic threshold grid + band classification
// ---------------------------------------------------------------------------
__global__ __launch_bounds__(256) void select_kernel(const float* __restrict__ W,
                                                     const float* __restrict__ bias) {
    __shared__ float s_w2[8];
    __shared__ int totals[16];
    __shared__ int sA, scnt;

    const int tid = threadIdx.x;
    const int o = blockIdx.x;

    float w2 = 0.f;
    const float4* wr4 = (const float4*)(W + (size_t)o * K_IN);
    for (int k = tid; k < K_IN / 4; k += 256) {
        const float4 wv = wr4[k];
        w2 += wv.x * wv.x + wv.y * wv.y + wv.z * wv.z + wv.w * wv.w;
    }
#pragma unroll
    for (int off = 16; off; off >>= 1) w2 += __shfl_xor_sync(0xffffffffu, w2, off);
    if ((tid & 31) == 0) s_w2[tid >> 5] = w2;
    if (tid < 16) totals[tid] = 0;
    if (tid == 0) { sA = 0; scnt = 0; }
    __syncthreads();
    float sig2 = 0.f;
#pragma unroll
    for (int i = 0; i < 8; i++) sig2 += s_w2[i];
    const float sigma = sqrtf(sig2);
    const float tc = bias[o] + ZC * sigma;
    const float step = ZSTEP * sigma;

    // load column (fp16) into registers
    const __half2* col = (const __half2*)(g_Lh + (size_t)o * N_BATCH);
    float v[16];
#pragma unroll
    for (int q = 0; q < 8; q++) {
        const float2 f = __half22float2(col[tid + 256 * q]);
        v[2 * q] = f.x;
        v[2 * q + 1] = f.y;
    }

    float t[16];
    int cnt[16];
#pragma unroll
    for (int i = 0; i < 16; i++) {
        t[i] = tc + (float)(i - 8) * step;
        cnt[i] = 0;
    }
#pragma unroll
    for (int q = 0; q < 16; q++) {
        const float x = v[q];
#pragma unroll
        for (int i = 0; i < 16; i++) cnt[i] += (x > t[i]) ? 1 : 0;
    }
#pragma unroll
    for (int i = 0; i < 16; i++) {
        const int s = __reduce_add_sync(0xffffffffu, cnt[i]);
        if ((tid & 31) == 0 && s) atomicAdd(&totals[i], s);
    }
    __syncthreads();

    int js = -1;
#pragma unroll
    for (int i = 0; i < 16; i++)
        if (totals[i] >= K_SEL) js = i;
    if (js < 0 || js == 15) {
        if (tid == 0) g_ucnt[o] = CAP + 1;   // exact fallback
        return;
    }
    const float T_hi = t[js + 1] + DELTA * sigma;
    const float T_lo = t[js] - DELTA * sigma;

    int a = 0;
#pragma unroll
    for (int q = 0; q < 16; q++) {
        const float x = v[q];
        if (x > T_hi) a++;
        else if (x > T_lo) {
            const int p = atomicAdd(&scnt, 1);
            if (p < CAP) {
                const int idx = 2 * (tid + 256 * (q >> 1)) + (q & 1);
                g_uidx[(size_t)o * CAP + p] = idx;
            }
        }
    }
    a = __reduce_add_sync(0xffffffffu, a);
    if ((tid & 31) == 0 && a) atomicAdd(&sA, a);
    __syncthreads();
    if (tid == 0) {
        if (scnt > CAP) {
            g_ucnt[o] = CAP + 1;
        } else {
            g_ucnt[o] = scnt;
            g_r[o] = K_SEL - sA;
            g_Thi[o] = T_hi;
        }
    }
}

// ---------------------------------------------------------------------------
// 4) mask: out[b][o] = (logit > Thi[o]); 64(b) x 32(o) transpose tiles
// ---------------------------------------------------------------------------
__global__ __launch_bounds__(256) void mask_kernel(float* __restrict__ out) {
    __shared__ uint32_t tile[32][33];   // tile[o_local][b_pair] = half2
    __shared__ float sth[32];
    const int tx = threadIdx.x, ty = threadIdx.y;
    const int b0 = blockIdx.x * 64, o0 = blockIdx.y * 32;

    if (ty == 0) sth[tx] = g_Thi[o0 + tx];
#pragma unroll
    for (int r = ty; r < 32; r += 8)
        tile[r][tx] = *(const uint32_t*)(g_Lh + (size_t)(o0 + r) * N_BATCH + b0 + 2 * tx);
    __syncthreads();

    const float th = sth[tx];
#pragma unroll
    for (int bl = ty; bl < 64; bl += 8) {
        const uint32_t u = tile[tx][bl >> 1];
        const __half h = ((const __half*)&u)[bl & 1];
        out[(size_t)(b0 + bl) * M_OUT + o0 + tx] =
            (__half2float(h) > th) ? 1.0f : 0.0f;
    }
}

// ---------------------------------------------------------------------------
// 5) repair: exact fp32 ascending-k chain on uncertain elements
// ---------------------------------------------------------------------------
__global__ __launch_bounds__(256) void repair_kernel(const float* __restrict__ W,
                                                     const float* __restrict__ X,
                                                     const float* __restrict__ bias,
                                                     float* __restrict__ out) {
    const int o = blockIdx.x;
    const int tid = threadIdx.x;
    const int c = g_ucnt[o];
    if (c == 0) return;

    const float4* wr4 = (const float4*)(W + (size_t)o * K_IN);

    if (c <= CAP) {
        __shared__ float vals[CAP];
        __shared__ int idxs[CAP];
        if (tid < c) {
            const int b = g_uidx[(size_t)o * CAP + tid];
            const float4* xr4 = (const float4*)(X + (size_t)b * K_IN);
            float acc = 0.f;
            for (int k = 0; k < K_IN / 4; k++) {
                const float4 wv = wr4[k], xv = xr4[k];
                acc = __fmaf_rn(wv.x, xv.x, acc);
                acc = __fmaf_rn(wv.y, xv.y, acc);
                acc = __fmaf_rn(wv.z, xv.z, acc);
                acc = __fmaf_rn(wv.w, xv.w, acc);
            }
            vals[tid] = acc + bias[o];
            idxs[tid] = b;
        }
        __syncthreads();
        if (tid == 0) {
            const int r = g_r[o];
            ull taken = 0;
            for (int rep = 0; rep < r; rep++) {
                int best = -1;
                for (int j = 0; j < c; j++) {
                    if ((taken >> j) & 1ull) continue;
                    if (best < 0 || vals[j] > vals[best] ||
                        (vals[j] == vals[best] && idxs[j] < idxs[best]))
                        best = j;
                }
                if (best < 0) break;
                taken |= 1ull << best;
                out[(size_t)idxs[best] * M_OUT + o] = 1.0f;
            }
        }
        return;
    }

    // fallback: recompute whole column exactly + exact radix select with ties
    __shared__ unsigned keys[N_BATCH];
    __shared__ unsigned hist[256];
    __shared__ unsigned s_prefix;
    __shared__ int s_rem, s_cut;
    for (int b = tid; b < N_BATCH; b += 256) {
        const float4* xr4 = (const float4*)(X + (size_t)b * K_IN);
        float acc = 0.f;
        for (int k = 0; k < K_IN / 4; k++) {
            const float4 wv = wr4[k], xv = xr4[k];
            acc = __fmaf_rn(wv.x, xv.x, acc);
            acc = __fmaf_rn(wv.y, xv.y, acc);
            acc = __fmaf_rn(wv.z, xv.z, acc);
            acc = __fmaf_rn(wv.w, xv.w, acc);
        }
        const float f = acc + bias[o];
        const unsigned u = __float_as_uint(f);
        keys[b] = u ^ ((u & 0x80000000u) ? 0xFFFFFFFFu : 0x80000000u);
    }
    if (tid == 0) { s_prefix = 0u; s_rem = K_SEL; }
    const unsigned himasks[4] = {0u, 0xFF000000u, 0xFFFF0000u, 0xFFFFFF00u};
#pragma unroll
    for (int pass = 0; pass < 4; pass++) {
        const int shift = 24 - 8 * pass;
        __syncthreads();
        hist[tid] = 0;
        __syncthreads();
        const unsigned hm = himasks[pass];
        const unsigned pfx = s_prefix;
        for (int i = tid; i < N_BATCH; i += 256) {
            const unsigned u = keys[i];
            if ((u & hm) == (pfx & hm)) atomicAdd(&hist[(u >> shift) & 255], 1u);
        }
        __syncthreads();
        if (tid == 0) {
            unsigned cum = 0;
            int d;
            for (d = 255; d >= 0; d--) {
                cum += hist[d];
                if ((int)cum >= s_rem) break;
            }
            s_rem -= (int)(cum - hist[d]);
            s_prefix = pfx | ((unsigned)d << shift);
        }
    }
    __syncthreads();
    const unsigned tau = s_prefix;
    const int rem = s_rem;
    const int base = tid * 16;
    int cnt = 0;
#pragma unroll
    for (int j = 0; j < 16; j++) cnt += (keys[base + j] == tau) ? 1 : 0;
    __syncthreads();
    hist[tid] = (unsigned)cnt;
    __syncthreads();
    for (int off = 1; off < 256; off <<= 1) {
        const unsigned v = hist[tid];
        const unsigned a = (tid >= off) ? hist[tid - off] : 0u;
        __syncthreads();
        hist[tid] = v + a;
        __syncthreads();
    }
    const int incl = (int)hist[tid];
    const int excl = incl - cnt;
    if (excl < rem && rem <= incl) {
        int need = rem - excl;
        for (int j = 0; j < 16; j++) {
            if (keys[base + j] == tau && --need == 0) { s_cut = base + j; break; }
        }
    }
    __syncthreads();
    const int cut = s_cut;
    for (int b = tid; b < N_BATCH; b += 256) {
        const unsigned k = keys[b];
        out[(size_t)b * M_OUT + o] = (k > tau || (k == tau && b <= cut)) ? 1.0f : 0.0f;
    }
}

// ---------------------------------------------------------------------------
extern "C" void kernel_launch(void* const* d_in, const int* in_sizes, int n_in,
                              void* d_out, int out_size) {
    const float* x = (const float*)d_in[0];  // [4096, 512]
    const float* W = (const float*)d_in[1];  // [8192, 512]
    const float* b = (const float*)d_in[2];  // [8192]
    float* out = (float*)d_out;              // [4096, 8192]

    split_kernel<<<(unsigned)((WQ + XQ + 255) / 256), 256>>>(W, x);
    gemm_kernel<<<dim3(N_BATCH / TN, M_OUT / TM), 256>>>(b);
    select_kernel<<<M_OUT, 256>>>(W, b);
    mask_kernel<<<dim3(N_BATCH / 64, M_OUT / 32), dim3(32, 8)>>>(out);
    repair_kernel<<<M_OUT, 256>>>(W, x, b, out);
}